// round 1
// baseline (speedup 1.0000x reference)
#include <cuda_runtime.h>

#define B_    4
#define T_    1024
#define DIM_  512
#define POOL_ 64
#define K_    50

// Scratch (device globals: allocation-free per harness rules)
__device__ __align__(16) float g_y[B_ * POOL_ * POOL_];   // y[b][t<64][p]
__device__ int   g_idx[T_ * K_];                          // top-50 indices per t
__device__ __align__(16) float g_z[B_ * POOL_ * DIM_];    // z[b][j][d]

// ---------------------------------------------------------------------------
// Kernel 1: per token t — Linear(512->64)+ReLU+LN for all 4 batches,
// sum over batch, stable top-50 ranking of 64 values.
// grid = T_, block = 64
// ---------------------------------------------------------------------------
__global__ void k1_reduce_topk(const float* __restrict__ x,
                               const float* __restrict__ w1,
                               const float* __restrict__ b1,
                               const float* __restrict__ g1,
                               const float* __restrict__ bt1) {
    const int t = blockIdx.x;
    const int p = threadIdx.x;   // 0..63, one pool output per thread

    __shared__ float4 xs[B_][DIM_ / 4];   // 4 x-rows, 8KB
    #pragma unroll
    for (int b = 0; b < B_; b++) {
        const float4* xr = reinterpret_cast<const float4*>(
            x + ((size_t)b * T_ + t) * DIM_);
        xs[b][p]      = xr[p];
        xs[b][p + 64] = xr[p + 64];
    }
    __syncthreads();

    float acc[B_] = {0.f, 0.f, 0.f, 0.f};
    #pragma unroll 4
    for (int d4 = 0; d4 < DIM_ / 4; d4++) {
        const float* wp = w1 + (d4 * 4) * POOL_ + p;   // coalesced across p
        float wa = wp[0];
        float wb = wp[POOL_];
        float wc = wp[2 * POOL_];
        float wd = wp[3 * POOL_];
        #pragma unroll
        for (int b = 0; b < B_; b++) {
            float4 v = xs[b][d4];
            acc[b] += v.x * wa + v.y * wb + v.z * wc + v.w * wd;
        }
    }

    // bias + relu
    const float bias = b1[p];
    float vv[B_];
    #pragma unroll
    for (int b = 0; b < B_; b++) vv[b] = fmaxf(acc[b] + bias, 0.f);

    // LayerNorm over the 64 pool outputs (per batch), block = 2 warps
    float s[B_], q[B_];
    #pragma unroll
    for (int b = 0; b < B_; b++) { s[b] = vv[b]; q[b] = vv[b] * vv[b]; }
    #pragma unroll
    for (int off = 16; off > 0; off >>= 1) {
        #pragma unroll
        for (int b = 0; b < B_; b++) {
            s[b] += __shfl_xor_sync(0xffffffffu, s[b], off);
            q[b] += __shfl_xor_sync(0xffffffffu, q[b], off);
        }
    }
    __shared__ float wsum[2][B_], wsq[2][B_];
    const int w = p >> 5;
    if ((p & 31) == 0) {
        #pragma unroll
        for (int b = 0; b < B_; b++) { wsum[w][b] = s[b]; wsq[w][b] = q[b]; }
    }
    __syncthreads();

    const float gp = g1[p], bp = bt1[p];
    float yv[B_];
    float ysum = 0.f;
    #pragma unroll
    for (int b = 0; b < B_; b++) {
        float S = wsum[0][b] + wsum[1][b];
        float Q = wsq[0][b] + wsq[1][b];
        float m   = S * (1.f / POOL_);
        float var = Q * (1.f / POOL_) - m * m;
        float r   = rsqrtf(var + 1e-5f);
        yv[b] = (vv[b] - m) * r * gp + bp;
        ysum += yv[b];
    }

    // Only rows t<64 are ever gathered downstream
    if (t < POOL_) {
        #pragma unroll
        for (int b = 0; b < B_; b++)
            g_y[(b * POOL_ + t) * POOL_ + p] = yv[b];
    }

    // Stable top-50 of 64: rank = #{greater} + #{equal with lower index}
    __shared__ float sv[POOL_];
    sv[p] = ysum;
    __syncthreads();
    const float mine = ysum;
    int rank = 0;
    #pragma unroll
    for (int j = 0; j < POOL_; j++) {
        float o = sv[j];
        rank += (o > mine) || ((o == mine) && (j < p));
    }
    if (rank < K_) g_idx[t * K_ + rank] = p;
}

// ---------------------------------------------------------------------------
// Kernel 2: z[b,j,:] = LN(relu(y[b,j,:] @ w2 + b2))   (256 distinct rows)
// grid = B_*POOL_, block = 512
// ---------------------------------------------------------------------------
__global__ void k2_expand(const float* __restrict__ w2,
                          const float* __restrict__ b2,
                          const float* __restrict__ g2,
                          const float* __restrict__ bt2) {
    const int bj = blockIdx.x;     // b*64 + j
    const int d  = threadIdx.x;    // 0..511

    __shared__ float yr[POOL_];
    if (d < POOL_) yr[d] = g_y[bj * POOL_ + d];
    __syncthreads();

    float acc = b2[d];
    #pragma unroll
    for (int p = 0; p < POOL_; p++)
        acc += yr[p] * w2[p * DIM_ + d];   // coalesced across d

    float v = fmaxf(acc, 0.f);

    // block LN over 512
    float s = v, q = v * v;
    #pragma unroll
    for (int off = 16; off > 0; off >>= 1) {
        s += __shfl_xor_sync(0xffffffffu, s, off);
        q += __shfl_xor_sync(0xffffffffu, q, off);
    }
    __shared__ float ps[16], pq[16];
    const int w = d >> 5;
    if ((d & 31) == 0) { ps[w] = s; pq[w] = q; }
    __syncthreads();
    float S = 0.f, Q = 0.f;
    #pragma unroll
    for (int i = 0; i < 16; i++) { S += ps[i]; Q += pq[i]; }

    float m   = S * (1.f / DIM_);
    float var = Q * (1.f / DIM_) - m * m;
    g_z[bj * DIM_ + d] = (v - m) * rsqrtf(var + 1e-5f) * g2[d] + bt2[d];
}

// ---------------------------------------------------------------------------
// Kernel 3: out[b,t,k,:] = z[b, idx[t,k], :]  — the 419 MB write stream.
// Warp-per-row float4 copy; z read via L1/L2 (__ldg), output with __stcs
// (streaming) so the write flood doesn't evict z from L2.
// grid = 204800/64 = 3200, block = 512 (16 warps, 64 rows/block)
// ---------------------------------------------------------------------------
__global__ void k3_gather(float* __restrict__ out) {
    const int warp = threadIdx.x >> 5;
    const int lane = threadIdx.x & 31;
    const unsigned base = blockIdx.x * 64u;

    #pragma unroll
    for (int i = 0; i < 4; i++) {
        unsigned r   = base + warp + i * 16;         // global row in [0, 204800)
        unsigned b   = r / (unsigned)(T_ * K_);      // 51200
        unsigned rem = r - b * (unsigned)(T_ * K_);
        unsigned t   = rem / K_;
        unsigned k   = rem - t * K_;
        int j = g_idx[t * K_ + k];

        const float4* src = reinterpret_cast<const float4*>(g_z)
                            + (size_t)(b * POOL_ + j) * (DIM_ / 4);
        float4* dst = reinterpret_cast<float4*>(out)
                      + (size_t)r * (DIM_ / 4);
        #pragma unroll
        for (int c = 0; c < 4; c++) {
            float4 v = __ldg(src + lane + 32 * c);
            __stcs(dst + lane + 32 * c, v);
        }
    }
}

// ---------------------------------------------------------------------------
extern "C" void kernel_launch(void* const* d_in, const int* in_sizes, int n_in,
                              void* d_out, int out_size) {
    const float* x   = (const float*)d_in[0];
    const float* w1  = (const float*)d_in[1];
    const float* b1  = (const float*)d_in[2];
    const float* g1  = (const float*)d_in[3];
    const float* bt1 = (const float*)d_in[4];
    const float* w2  = (const float*)d_in[5];
    const float* b2  = (const float*)d_in[6];
    const float* g2  = (const float*)d_in[7];
    const float* bt2 = (const float*)d_in[8];
    float* out = (float*)d_out;

    k1_reduce_topk<<<T_, POOL_>>>(x, w1, b1, g1, bt1);
    k2_expand<<<B_ * POOL_, DIM_>>>(w2, b2, g2, bt2);
    k3_gather<<<(B_ * T_ * K_) / 64, 512>>>(out);
}

// round 2
// speedup vs baseline: 1.1555x; 1.1555x over previous
#include <cuda_runtime.h>

#define B_    4
#define T_    1024
#define DIM_  512
#define POOL_ 64
#define K_    50

// Scratch (device globals: allocation-free per harness rules)
__device__ __align__(16) float g_y[B_ * POOL_ * POOL_];   // y[b][t<64][p]
__device__ int   g_idx[T_ * K_];                          // top-50 indices per t
__device__ __align__(16) float g_z[B_ * POOL_ * DIM_];    // z[b][j][d]

// ---------------------------------------------------------------------------
// Kernel 1: per token t — Linear(512->64)+ReLU+LN for all 4 batches,
// sum over batch, stable top-50 ranking of 64 values.
// grid = T_, block = 256: tid = p + 64*c, chunk c reduces dims [c*128,(c+1)*128)
// ---------------------------------------------------------------------------
__global__ __launch_bounds__(256) void k1_reduce_topk(
        const float* __restrict__ x,
        const float* __restrict__ w1,
        const float* __restrict__ b1,
        const float* __restrict__ g1,
        const float* __restrict__ bt1) {
    const int t   = blockIdx.x;
    const int tid = threadIdx.x;
    const int p   = tid & 63;    // pool output index
    const int c   = tid >> 6;    // DIM chunk 0..3

    __shared__ float4 xs[B_][DIM_ / 4];          // 4 x-rows, 8KB
    __shared__ float  part[B_][4][POOL_];        // partial dots, 4KB

    #pragma unroll
    for (int i = tid; i < B_ * (DIM_ / 4); i += 256) {
        int b = i >> 7, j = i & 127;
        xs[b][j] = reinterpret_cast<const float4*>(
            x + ((size_t)b * T_ + t) * DIM_)[j];
    }
    __syncthreads();

    // each thread: 128-dim partial dot for (p, all 4 batches)
    float acc[B_] = {0.f, 0.f, 0.f, 0.f};
    const float* wbase = w1 + (c * 128) * POOL_ + p;
    #pragma unroll 8
    for (int d4 = 0; d4 < 32; d4++) {
        const float* wp = wbase + d4 * 4 * POOL_;
        float wa = wp[0];
        float wb = wp[POOL_];
        float wc = wp[2 * POOL_];
        float wd = wp[3 * POOL_];
        #pragma unroll
        for (int b = 0; b < B_; b++) {
            float4 v = xs[b][c * 32 + d4];
            acc[b] += v.x * wa + v.y * wb + v.z * wc + v.w * wd;
        }
    }
    #pragma unroll
    for (int b = 0; b < B_; b++) part[b][c][p] = acc[b];
    __syncthreads();

    // ---- tail on first 64 threads (2 warps) ----
    if (tid < 64) {
        const float bias = b1[p];
        float vv[B_];
        #pragma unroll
        for (int b = 0; b < B_; b++) {
            float a = part[b][0][p] + part[b][1][p]
                    + part[b][2][p] + part[b][3][p] + bias;
            vv[b] = fmaxf(a, 0.f);
        }

        // LayerNorm over the 64 pool outputs (per batch)
        float s[B_], q[B_];
        #pragma unroll
        for (int b = 0; b < B_; b++) { s[b] = vv[b]; q[b] = vv[b] * vv[b]; }
        #pragma unroll
        for (int off = 16; off > 0; off >>= 1) {
            #pragma unroll
            for (int b = 0; b < B_; b++) {
                s[b] += __shfl_xor_sync(0xffffffffu, s[b], off);
                q[b] += __shfl_xor_sync(0xffffffffu, q[b], off);
            }
        }
        __shared__ float wsum[2][B_], wsq[2][B_];
        const int w = p >> 5;
        if ((p & 31) == 0) {
            #pragma unroll
            for (int b = 0; b < B_; b++) { wsum[w][b] = s[b]; wsq[w][b] = q[b]; }
        }
        __syncwarp();
        // cross-warp visibility for the 2 participating warps
        asm volatile("bar.sync 1, 64;" ::: "memory");

        const float gp = g1[p], bp = bt1[p];
        float yv[B_];
        float ysum = 0.f;
        #pragma unroll
        for (int b = 0; b < B_; b++) {
            float S = wsum[0][b] + wsum[1][b];
            float Q = wsq[0][b] + wsq[1][b];
            float m   = S * (1.f / POOL_);
            float var = Q * (1.f / POOL_) - m * m;
            float r   = rsqrtf(var + 1e-5f);
            yv[b] = (vv[b] - m) * r * gp + bp;
            ysum += yv[b];
        }

        // Only rows t<64 are ever gathered downstream
        if (t < POOL_) {
            #pragma unroll
            for (int b = 0; b < B_; b++)
                g_y[(b * POOL_ + t) * POOL_ + p] = yv[b];
        }

        // Stable top-50 of 64: rank = #{greater} + #{equal with lower index}
        __shared__ float sv[POOL_];
        sv[p] = ysum;
        asm volatile("bar.sync 1, 64;" ::: "memory");
        const float mine = ysum;
        int rank = 0;
        #pragma unroll
        for (int j = 0; j < POOL_; j++) {
            float o = sv[j];
            rank += (o > mine) || ((o == mine) && (j < p));
        }
        if (rank < K_) g_idx[t * K_ + rank] = p;
    }
}

// ---------------------------------------------------------------------------
// Kernel 2: z[b,j,:] = LN(relu(y[b,j,:] @ w2 + b2))   (256 distinct rows)
// grid = B_*POOL_, block = 512
// ---------------------------------------------------------------------------
__global__ void k2_expand(const float* __restrict__ w2,
                          const float* __restrict__ b2,
                          const float* __restrict__ g2,
                          const float* __restrict__ bt2) {
    const int bj = blockIdx.x;     // b*64 + j
    const int d  = threadIdx.x;    // 0..511

    __shared__ float yr[POOL_];
    if (d < POOL_) yr[d] = g_y[bj * POOL_ + d];
    __syncthreads();

    float acc = b2[d];
    #pragma unroll
    for (int p = 0; p < POOL_; p++)
        acc += yr[p] * w2[p * DIM_ + d];   // coalesced across d

    float v = fmaxf(acc, 0.f);

    // block LN over 512
    float s = v, q = v * v;
    #pragma unroll
    for (int off = 16; off > 0; off >>= 1) {
        s += __shfl_xor_sync(0xffffffffu, s, off);
        q += __shfl_xor_sync(0xffffffffu, q, off);
    }
    __shared__ float ps[16], pq[16];
    const int w = d >> 5;
    if ((d & 31) == 0) { ps[w] = s; pq[w] = q; }
    __syncthreads();
    float S = 0.f, Q = 0.f;
    #pragma unroll
    for (int i = 0; i < 16; i++) { S += ps[i]; Q += pq[i]; }

    float m   = S * (1.f / DIM_);
    float var = Q * (1.f / DIM_) - m * m;
    g_z[bj * DIM_ + d] = (v - m) * rsqrtf(var + 1e-5f) * g2[d] + bt2[d];
}

// ---------------------------------------------------------------------------
// Kernel 3: out[b,t,k,:] = z[b, idx[t,k], :]  — the 419 MB write stream.
// Warp-per-row float4 copy; z read via L1/L2 (__ldg), output with __stcs
// (streaming) so the write flood doesn't evict z from L2.
// grid = 204800/64 = 3200, block = 512 (16 warps, 64 rows/block)
// ---------------------------------------------------------------------------
__global__ void k3_gather(float* __restrict__ out) {
    const int warp = threadIdx.x >> 5;
    const int lane = threadIdx.x & 31;
    const unsigned base = blockIdx.x * 64u;

    #pragma unroll
    for (int i = 0; i < 4; i++) {
        unsigned r   = base + warp + i * 16;         // global row in [0, 204800)
        unsigned b   = r / (unsigned)(T_ * K_);      // 51200
        unsigned rem = r - b * (unsigned)(T_ * K_);
        unsigned t   = rem / K_;
        unsigned k   = rem - t * K_;
        int j = g_idx[t * K_ + k];

        const float4* src = reinterpret_cast<const float4*>(g_z)
                            + (size_t)(b * POOL_ + j) * (DIM_ / 4);
        float4* dst = reinterpret_cast<float4*>(out)
                      + (size_t)r * (DIM_ / 4);
        #pragma unroll
        for (int c = 0; c < 4; c++) {
            float4 v = __ldg(src + lane + 32 * c);
            __stcs(dst + lane + 32 * c, v);
        }
    }
}

// ---------------------------------------------------------------------------
extern "C" void kernel_launch(void* const* d_in, const int* in_sizes, int n_in,
                              void* d_out, int out_size) {
    const float* x   = (const float*)d_in[0];
    const float* w1  = (const float*)d_in[1];
    const float* b1  = (const float*)d_in[2];
    const float* g1  = (const float*)d_in[3];
    const float* bt1 = (const float*)d_in[4];
    const float* w2  = (const float*)d_in[5];
    const float* b2  = (const float*)d_in[6];
    const float* g2  = (const float*)d_in[7];
    const float* bt2 = (const float*)d_in[8];
    float* out = (float*)d_out;

    k1_reduce_topk<<<T_, 256>>>(x, w1, b1, g1, bt1);
    k2_expand<<<B_ * POOL_, DIM_>>>(w2, b2, g2, bt2);
    k3_gather<<<(B_ * T_ * K_) / 64, 512>>>(out);
}